// round 8
// baseline (speedup 1.0000x reference)
#include <cuda_runtime.h>
#include <cuda_fp16.h>
#include <cstdint>
#include <cstddef>
#include <math.h>

// ---------------------------------------------------------------------------
// GLN_56006373539841: HMMA fp16 GEMM, single-pass, 512-thread CTAs (16 warps)
// for latency hiding (R7 showed tensor=40%, occ=12.5% with 8 warps).
//   ctx GEMMs: fp16 + tau=0.08 fp64 rescue of near-threshold sign decisions
//   select GEMMs: single-pass fp16, hidden h stored fp16
//   B=4096, D_IN=1024, D_LAT=2048, D_OUT=1024, SHATTER=3, NC=8
// ---------------------------------------------------------------------------

#define RESCUE_TAU 0.08f
#define PITCH   80                    // 64B data + 16B pad (KC=32 fp16 rows)

// select GEMM (NT=128): 2 tiles (A, B), 4 stages
#define SSTAGES 4
#define S_TILE  (128 * PITCH)         // 10240
#define S_STAGE (2 * S_TILE)          // 20480
#define S_SMEM  (SSTAGES * S_STAGE)   // 81920

// ctx GEMM (NT=192): 2 tiles (A, B), 4 stages
#define CSTAGES 4
#define C_AB    (128 * PITCH)         // 10240
#define C_BB    (192 * PITCH)         // 15360
#define C_STAGE (C_AB + C_BB)         // 25600
#define C_SMEM  (CSTAGES * C_STAGE)   // 102400
#define SC_PITCH 194                  // score staging pitch (floats)

// ============================ PTX helpers ==================================
__device__ __forceinline__ uint32_t smem_u32(const void* p) {
    uint32_t a;
    asm("{ .reg .u64 t; cvta.to.shared.u64 t, %1; cvt.u32.u64 %0, t; }"
        : "=r"(a) : "l"(p));
    return a;
}
__device__ __forceinline__ void cp16(uint32_t dst, const void* src) {
    asm volatile("cp.async.cg.shared.global [%0], [%1], 16;" :: "r"(dst), "l"(src));
}
#define CP_COMMIT() asm volatile("cp.async.commit_group;" ::: "memory")

__device__ __forceinline__ void ldsm4(uint32_t* r, uint32_t addr) {
    asm volatile("ldmatrix.sync.aligned.m8n8.x4.shared.b16 {%0,%1,%2,%3}, [%4];"
        : "=r"(r[0]), "=r"(r[1]), "=r"(r[2]), "=r"(r[3]) : "r"(addr));
}
__device__ __forceinline__ void hmma(float* d, const uint32_t* a, const uint32_t* b) {
    asm volatile("mma.sync.aligned.m16n8k16.row.col.f32.f16.f16.f32 "
        "{%0,%1,%2,%3},{%4,%5,%6,%7},{%8,%9},{%0,%1,%2,%3};"
        : "+f"(d[0]), "+f"(d[1]), "+f"(d[2]), "+f"(d[3])
        : "r"(a[0]), "r"(a[1]), "r"(a[2]), "r"(a[3]), "r"(b[0]), "r"(b[1]));
}

// ============================ scratch ======================================
__device__ __half g_xh [4096u * 1024u];
__device__ __half g_hA [4096u * 2048u];
__device__ __half g_hB [4096u * 2048u];
__device__ __half g_whA[6144u * 1024u];     // H conversions (contexts)
__device__ __half g_whB[16384u * 2048u];    // W conversions (largest: W1)
__device__ unsigned char g_ctx0[4096u * 2048u];
__device__ unsigned char g_ctx1[4096u * 2048u];
__device__ unsigned char g_ctx2[4096u * 1024u];

// ============================ convert kernel ===============================
__global__ void conv_hi(const float* __restrict__ in, __half* __restrict__ hi, int n4)
{
    int i = blockIdx.x * blockDim.x + threadIdx.x;
    if (i >= n4) return;
    float4 v = ((const float4*)in)[i];
    ((__half2*)hi)[i * 2 + 0] = __halves2half2(__float2half_rn(v.x), __float2half_rn(v.y));
    ((__half2*)hi)[i * 2 + 1] = __halves2half2(__float2half_rn(v.z), __float2half_rn(v.w));
}

// ============================ ctx GEMM (fused combine) =====================
// CTA 128M x 192N, 16 warps (4M x 4N), warp tile 32x48.
// Output byte: bits 0-2 ctx index, bits 3-5 per-score rescue flags.
__global__ __launch_bounds__(512, 1)
void gemm_ctx(const __half* __restrict__ Ahi, const __half* __restrict__ Bhi,
              int K, int O,
              unsigned char* __restrict__ ctxout, const float* __restrict__ T)
{
    extern __shared__ char smraw[];
    const uint32_t smb = smem_u32(smraw);
    const int tid  = threadIdx.x;
    const int lane = tid & 31;
    const int wid  = tid >> 5;
    const int wm   = wid & 3;       // 0..3 (M)
    const int wn   = wid >> 2;      // 0..3 (N)
    const int row0 = blockIdx.x * 128;
    const int col0 = blockIdx.y * 192;

    const __half* gA = Ahi + (size_t)row0 * K;
    const __half* gB = Bhi + (size_t)col0 * K;

    float acc[2][6][4];
#pragma unroll
    for (int i = 0; i < 2; i++)
#pragma unroll
        for (int j = 0; j < 6; j++)
#pragma unroll
            for (int q = 0; q < 4; q++) acc[i][j][q] = 0.0f;

    const int nk = K >> 5;

    auto issue = [&](int s) {
        uint32_t base = smb + (uint32_t)(s & (CSTAGES - 1)) * C_STAGE;
        int k0 = s * 32;
        // A: 512 cp16 + B: 768 cp16 = 1280 total
#pragma unroll
        for (int t = 0; t < 3; t++) {
            int id = tid + t * 512;
            if (id < 512) {
                int r = id >> 2, c = id & 3;
                cp16(base + r * PITCH + c * 16, gA + (size_t)r * K + k0 + c * 8);
            } else if (id < 1280) {
                int j = id - 512;
                int r = j >> 2, c = j & 3;
                cp16(base + C_AB + r * PITCH + c * 16, gB + (size_t)r * K + k0 + c * 8);
            }
        }
        CP_COMMIT();
    };

#pragma unroll
    for (int s = 0; s < CSTAGES - 1; s++) issue(s);

    const uint32_t lrow = (uint32_t)(lane & 15);
    const uint32_t lhal = (uint32_t)(lane >> 4) * 16;

    for (int it = 0; it < nk; it++) {
        asm volatile("cp.async.wait_group 2;" ::: "memory");
        __syncthreads();
        int pf = it + CSTAGES - 1;
        if (pf < nk) issue(pf); else CP_COMMIT();

        uint32_t stg = smb + (uint32_t)(it & (CSTAGES - 1)) * C_STAGE;
#pragma unroll
        for (int k16 = 0; k16 < 2; k16++) {
            uint32_t koff = lhal + (uint32_t)k16 * 32;
            uint32_t ah[2][4];
#pragma unroll
            for (int mi = 0; mi < 2; mi++) {
                uint32_t ro = (uint32_t)(wm * 32 + mi * 16) + lrow;
                ldsm4(ah[mi], stg + ro * PITCH + koff);
            }
            uint32_t bh[6][2];
#pragma unroll
            for (int jj = 0; jj < 3; jj++) {
                uint32_t ro = (uint32_t)(wn * 48 + jj * 16) + lrow;
                uint32_t r4[4];
                ldsm4(r4, stg + C_AB + ro * PITCH + koff);
                bh[jj * 2][0] = r4[0]; bh[jj * 2][1] = r4[2];
                bh[jj * 2 + 1][0] = r4[1]; bh[jj * 2 + 1][1] = r4[3];
            }
#pragma unroll
            for (int mi = 0; mi < 2; mi++)
#pragma unroll
                for (int nj = 0; nj < 6; nj++) hmma(acc[mi][nj], ah[mi], bh[nj]);
        }
    }
    asm volatile("cp.async.wait_group 0;" ::: "memory");
    __syncthreads();

    // ---- stage scores into smem ----
    float* ssc = (float*)smraw;
    const int rr = lane >> 2;
    const int q2 = (lane & 3) * 2;
#pragma unroll
    for (int mi = 0; mi < 2; mi++) {
        int r_lo = wm * 32 + mi * 16 + rr;
        int r_hi = r_lo + 8;
#pragma unroll
        for (int nj = 0; nj < 6; nj++) {
            int c = wn * 48 + nj * 8 + q2;
            *(float2*)&ssc[r_lo * SC_PITCH + c] = make_float2(acc[mi][nj][0], acc[mi][nj][1]);
            *(float2*)&ssc[r_hi * SC_PITCH + c] = make_float2(acc[mi][nj][2], acc[mi][nj][3]);
        }
    }
    __syncthreads();

    // ---- combine: 128 rows x 64 o-groups -> 2048 uint32 words ----
    const int oc0 = col0 / 3;
#pragma unroll
    for (int w4 = 0; w4 < 4; w4++) {
        int word_id = tid + w4 * 512;
        int r  = word_id >> 4;
        int wo = word_id & 15;
        const float* sp = ssc + r * SC_PITCH + wo * 12;
        uint32_t word = 0;
#pragma unroll
        for (int j = 0; j < 4; j++) {
            int o = oc0 + wo * 4 + j;
            int c = 0;
#pragma unroll
            for (int s = 0; s < 3; s++) {
                float th = __ldg(T + o * 3 + s);
                float d  = sp[j * 3 + s] - th;
                c |= ((int)(d > 0.0f)) << s;
                c |= ((int)(fabsf(d) < RESCUE_TAU)) << (3 + s);
            }
            word |= (uint32_t)((unsigned char)c) << (j * 8);
        }
        *(uint32_t*)(ctxout + (size_t)(row0 + r) * O + oc0 + wo * 4) = word;
    }
}

// ============================ warp-cooperative fp64 rescue =================
__global__ void gln_rescue(unsigned char* __restrict__ ctx,
                           const float* __restrict__ z,
                           const float* __restrict__ H,
                           const float* __restrict__ T,
                           int total4, int O, int K)
{
    int i    = blockIdx.x * blockDim.x + threadIdx.x;
    int lane = threadIdx.x & 31;
    uint32_t w = (i < total4) ? ((const uint32_t*)ctx)[i] : 0u;
    unsigned m = __ballot_sync(0xFFFFFFFFu, (w & 0x38383838u) != 0u);
    while (m) {
        int src = __ffs(m) - 1; m &= m - 1;
        uint32_t sw = __shfl_sync(0xFFFFFFFFu, w, src);
        int si = __shfl_sync(0xFFFFFFFFu, i, src);
#pragma unroll
        for (int j = 0; j < 4; j++) {
            uint32_t byte = (sw >> (j * 8)) & 0xFF;
            if (!(byte & 0x38)) continue;
            int idx = si * 4 + j;
            int b = idx / O, o = idx - b * O;
            const float* zr = z + (size_t)b * K;
            int c = (int)(byte & 7);
#pragma unroll
            for (int s = 0; s < 3; s++) {
                if (!(byte & (8u << s))) continue;
                const float* hr = H + (size_t)(o * 3 + s) * K;
                double p0 = 0.0, p1 = 0.0;
                for (int k = lane; k < K; k += 64) {
                    p0 += (double)zr[k]      * (double)hr[k];
                    p1 += (double)zr[k + 32] * (double)hr[k + 32];
                }
                double part = p0 + p1;
#pragma unroll
                for (int off = 16; off; off >>= 1)
                    part += __shfl_down_sync(0xFFFFFFFFu, part, off);
                part = __shfl_sync(0xFFFFFFFFu, part, 0);
                c = (c & ~(1 << s)) | (((int)(part > (double)T[o * 3 + s])) << s);
            }
            if (lane == 0) ctx[idx] = (unsigned char)c;
        }
    }
}

// ============================ select GEMM ==================================
// CTA 128x128, 16 warps (4M x 4N), warp tile 32x32.
// MODE 1: hidden -> fp16.  MODE 2: final -> fp32.
template <int MODE>
__global__ __launch_bounds__(512, 1)
void gemm_sel(const __half* __restrict__ Ahi, const __half* __restrict__ Bhi,
              int K, int O,
              const unsigned char* __restrict__ ctx, const float* __restrict__ bias,
              float* __restrict__ outf, __half* __restrict__ outh)
{
    extern __shared__ char smraw[];
    const uint32_t smb = smem_u32(smraw);
    const int tid  = threadIdx.x;
    const int lane = tid & 31;
    const int wid  = tid >> 5;
    const int wm   = wid & 3;
    const int wn   = wid >> 2;      // 0..3
    const int row0 = blockIdx.x * 128;
    const int col0 = blockIdx.y * 128;

    const __half* gA = Ahi + (size_t)row0 * K;
    const __half* gB = Bhi + (size_t)col0 * K;

    float acc[2][4][4];
#pragma unroll
    for (int i = 0; i < 2; i++)
#pragma unroll
        for (int j = 0; j < 4; j++)
#pragma unroll
            for (int q = 0; q < 4; q++) acc[i][j][q] = 0.0f;

    const int nk = K >> 5;

    auto issue = [&](int s) {
        uint32_t base = smb + (uint32_t)(s & (SSTAGES - 1)) * S_STAGE;
        int k0 = s * 32;
#pragma unroll
        for (int t = 0; t < 2; t++) {           // 1024 cp16
            int id   = tid + t * 512;
            int tile = id >> 9;                 // 0..1
            int r    = (id >> 2) & 127;
            int c    = id & 3;
            const __half* g = tile ? gB : gA;
            cp16(base + tile * S_TILE + r * PITCH + c * 16,
                 g + (size_t)r * K + k0 + c * 8);
        }
        CP_COMMIT();
    };

#pragma unroll
    for (int s = 0; s < SSTAGES - 1; s++) issue(s);

    const uint32_t lrow = (uint32_t)(lane & 15);
    const uint32_t lhal = (uint32_t)(lane >> 4) * 16;

    for (int it = 0; it < nk; it++) {
        asm volatile("cp.async.wait_group 2;" ::: "memory");
        __syncthreads();
        int pf = it + SSTAGES - 1;
        if (pf < nk) issue(pf); else CP_COMMIT();

        uint32_t stg = smb + (uint32_t)(it & (SSTAGES - 1)) * S_STAGE;
#pragma unroll
        for (int k16 = 0; k16 < 2; k16++) {
            uint32_t koff = lhal + (uint32_t)k16 * 32;
            uint32_t ah[2][4];
#pragma unroll
            for (int mi = 0; mi < 2; mi++) {
                uint32_t ro = (uint32_t)(wm * 32 + mi * 16) + lrow;
                ldsm4(ah[mi], stg + ro * PITCH + koff);
            }
            uint32_t bh[4][2];
#pragma unroll
            for (int jj = 0; jj < 2; jj++) {
                uint32_t ro = (uint32_t)(wn * 32 + jj * 16) + lrow;
                uint32_t r4[4];
                ldsm4(r4, stg + S_TILE + ro * PITCH + koff);
                bh[jj * 2][0] = r4[0]; bh[jj * 2][1] = r4[2];
                bh[jj * 2 + 1][0] = r4[1]; bh[jj * 2 + 1][1] = r4[3];
            }
#pragma unroll
            for (int mi = 0; mi < 2; mi++)
#pragma unroll
                for (int nj = 0; nj < 4; nj++) hmma(acc[mi][nj], ah[mi], bh[nj]);
        }
    }

    // ---- 1-of-8 select epilogue ----
    const int rr = lane >> 2;
    const int q2 = (lane & 3) * 2;
#pragma unroll
    for (int mi = 0; mi < 2; mi++) {
        int r_lo = row0 + wm * 32 + mi * 16 + rr;
        int r_hi = r_lo + 8;
#pragma unroll
        for (int nj = 0; nj < 4; nj++) {
            int o   = (col0 + wn * 32 + nj * 8) >> 3;
            int cb0 = ctx[(size_t)r_lo * O + o] & 7;
            int cb1 = ctx[(size_t)r_hi * O + o] & 7;
            if (cb0 == q2 || cb0 == q2 + 1) {
                float v = (cb0 == q2) ? acc[mi][nj][0] : acc[mi][nj][1];
                if (bias) v += bias[o * 8 + cb0];
                size_t idx = (size_t)r_lo * O + o;
                if (MODE == 1) outh[idx] = __float2half_rn(v);
                else           outf[idx] = v;
            }
            if (cb1 == q2 || cb1 == q2 + 1) {
                float v = (cb1 == q2) ? acc[mi][nj][2] : acc[mi][nj][3];
                if (bias) v += bias[o * 8 + cb1];
                size_t idx = (size_t)r_hi * O + o;
                if (MODE == 1) outh[idx] = __float2half_rn(v);
                else           outf[idx] = v;
            }
        }
    }
}

// ============================ host =========================================
extern "C" void kernel_launch(void* const* d_in, const int* in_sizes, int n_in,
                              void* d_out, int out_size)
{
    const float* x  = (const float*)d_in[0];
    const float* W0 = (const float*)d_in[1];
    const float* W1 = (const float*)d_in[2];
    const float* W2 = (const float*)d_in[3];
    const float* b1 = (const float*)d_in[4];
    const float* b2 = (const float*)d_in[5];
    const float* H0 = (const float*)d_in[6];
    const float* T0 = (const float*)d_in[7];
    const float* H1 = (const float*)d_in[8];
    const float* T1 = (const float*)d_in[9];
    const float* H2 = (const float*)d_in[10];
    const float* T2 = (const float*)d_in[11];
    float* out = (float*)d_out;

    void *pxh, *pa, *pb, *pwa, *pwb, *pc0, *pc1, *pc2;
    cudaGetSymbolAddress(&pxh, g_xh);
    cudaGetSymbolAddress(&pa,  g_hA);  cudaGetSymbolAddress(&pb,  g_hB);
    cudaGetSymbolAddress(&pwa, g_whA); cudaGetSymbolAddress(&pwb, g_whB);
    cudaGetSymbolAddress(&pc0, g_ctx0); cudaGetSymbolAddress(&pc1, g_ctx1);
    cudaGetSymbolAddress(&pc2, g_ctx2);
    __half* xh  = (__half*)pxh;
    __half* hA  = (__half*)pa;   __half* hB  = (__half*)pb;
    __half* whA = (__half*)pwa;  __half* whB = (__half*)pwb;
    unsigned char* c0 = (unsigned char*)pc0;
    unsigned char* c1 = (unsigned char*)pc1;
    unsigned char* c2 = (unsigned char*)pc2;

    const int B = 4096, DIN = 1024, DLAT = 2048, DOUT = 1024;

    cudaFuncSetAttribute(gemm_ctx,    cudaFuncAttributeMaxDynamicSharedMemorySize, C_SMEM);
    cudaFuncSetAttribute(gemm_sel<1>, cudaFuncAttributeMaxDynamicSharedMemorySize, S_SMEM);
    cudaFuncSetAttribute(gemm_sel<2>, cudaFuncAttributeMaxDynamicSharedMemorySize, S_SMEM);

    auto conv = [](const float* in, __half* dst, size_t n) {
        int n4 = (int)(n / 4);
        conv_hi<<<(n4 + 255) / 256, 256>>>(in, dst, n4);
    };

    // Launch order keeps the profiled launch (0-based #3) on gemm_ctx.
    conv(x,  xh,  (size_t)B * DIN);                                  // 0
    conv(H0, whA, (size_t)DLAT * 3 * DIN);                           // 1
    conv(W0, whB, (size_t)DLAT * 8 * DIN);                           // 2
    gemm_ctx<<<dim3(B / 128, (DLAT * 3) / 192), 512, C_SMEM>>>(      // 3
        xh, whA, DIN, DLAT, c0, T0);
    gln_rescue<<<(B * DLAT / 4 + 255) / 256, 256>>>(                 // 4
        c0, x, H0, T0, B * DLAT / 4, DLAT, DIN);
    gemm_sel<1><<<dim3(B / 128, (DLAT * 8) / 128), 512, S_SMEM>>>(   // 5
        xh, whB, DIN, DLAT, c0, nullptr, nullptr, hA);

    conv(H1, whA, (size_t)DLAT * 3 * DIN);                           // 6
    gemm_ctx<<<dim3(B / 128, (DLAT * 3) / 192), 512, C_SMEM>>>(      // 7
        xh, whA, DIN, DLAT, c1, T1);
    gln_rescue<<<(B * DLAT / 4 + 255) / 256, 256>>>(                 // 8
        c1, x, H1, T1, B * DLAT / 4, DLAT, DIN);
    conv(W1, whB, (size_t)DLAT * 8 * DLAT);                          // 9
    gemm_sel<1><<<dim3(B / 128, (DLAT * 8) / 128), 512, S_SMEM>>>(   // 10
        hA, whB, DLAT, DLAT, c1, b1, nullptr, hB);

    conv(H2, whA, (size_t)DOUT * 3 * DIN);                           // 11
    gemm_ctx<<<dim3(B / 128, (DOUT * 3) / 192), 512, C_SMEM>>>(      // 12
        xh, whA, DIN, DOUT, c2, T2);
    gln_rescue<<<(B * DOUT / 4 + 255) / 256, 256>>>(                 // 13
        c2, x, H2, T2, B * DOUT / 4, DOUT, DIN);
    conv(W2, whB, (size_t)DOUT * 8 * DLAT);                          // 14
    gemm_sel<2><<<dim3(B / 128, (DOUT * 8) / 128), 512, S_SMEM>>>(   // 15
        hB, whB, DLAT, DOUT, c2, b2, out, nullptr);

    (void)in_sizes; (void)n_in; (void)out_size;
}

// round 10
// speedup vs baseline: 1.1185x; 1.1185x over previous
#include <cuda_runtime.h>
#include <cuda_fp16.h>
#include <cstdint>
#include <cstddef>
#include <math.h>

// ---------------------------------------------------------------------------
// GLN_56006373539841: HMMA fp16 GEMM, single-pass (R7 config) + 2-CTA/SM
// select GEMMs (3-stage smem, launch_bounds(256,2), wait_group 1 -- R9 had
// wait_group 2 with only 2 prefetched groups = race = NaN).
//   ctx GEMMs: fp16 + tau=0.08 fp64 rescue of near-threshold sign decisions
//   select GEMMs: single-pass fp16, hidden h stored fp16
//   B=4096, D_IN=1024, D_LAT=2048, D_OUT=1024, SHATTER=3, NC=8
// ---------------------------------------------------------------------------

#define RESCUE_TAU 0.08f
#define PITCH   80                    // 64B data + 16B pad (KC=32 fp16 rows)

// select GEMM (NT=128): 2 tiles (A, B), 3 stages -> 2 CTAs/SM
#define SSTAGES 3
#define S_TILE  (128 * PITCH)         // 10240
#define S_STAGE (2 * S_TILE)          // 20480
#define S_SMEM  (SSTAGES * S_STAGE)   // 61440

// ctx GEMM (NT=192): 2 tiles (A, B), 4 stages (1 CTA/SM, reg-heavy)
#define CSTAGES 4
#define C_AB    (128 * PITCH)         // 10240
#define C_BB    (192 * PITCH)         // 15360
#define C_STAGE (C_AB + C_BB)         // 25600
#define C_SMEM  (CSTAGES * C_STAGE)   // 102400
#define SC_PITCH 194                  // score staging pitch (floats)

// ============================ PTX helpers ==================================
__device__ __forceinline__ uint32_t smem_u32(const void* p) {
    uint32_t a;
    asm("{ .reg .u64 t; cvta.to.shared.u64 t, %1; cvt.u32.u64 %0, t; }"
        : "=r"(a) : "l"(p));
    return a;
}
__device__ __forceinline__ void cp16(uint32_t dst, const void* src) {
    asm volatile("cp.async.cg.shared.global [%0], [%1], 16;" :: "r"(dst), "l"(src));
}
#define CP_COMMIT() asm volatile("cp.async.commit_group;" ::: "memory")

__device__ __forceinline__ void ldsm4(uint32_t* r, uint32_t addr) {
    asm volatile("ldmatrix.sync.aligned.m8n8.x4.shared.b16 {%0,%1,%2,%3}, [%4];"
        : "=r"(r[0]), "=r"(r[1]), "=r"(r[2]), "=r"(r[3]) : "r"(addr));
}
__device__ __forceinline__ void hmma(float* d, const uint32_t* a, const uint32_t* b) {
    asm volatile("mma.sync.aligned.m16n8k16.row.col.f32.f16.f16.f32 "
        "{%0,%1,%2,%3},{%4,%5,%6,%7},{%8,%9},{%0,%1,%2,%3};"
        : "+f"(d[0]), "+f"(d[1]), "+f"(d[2]), "+f"(d[3])
        : "r"(a[0]), "r"(a[1]), "r"(a[2]), "r"(a[3]), "r"(b[0]), "r"(b[1]));
}

// ============================ scratch ======================================
__device__ __half g_xh [4096u * 1024u];
__device__ __half g_hA [4096u * 2048u];
__device__ __half g_hB [4096u * 2048u];
__device__ __half g_whA[6144u * 1024u];     // H conversions (contexts)
__device__ __half g_whB[16384u * 2048u];    // W conversions (largest: W1)
__device__ unsigned char g_ctx0[4096u * 2048u];
__device__ unsigned char g_ctx1[4096u * 2048u];
__device__ unsigned char g_ctx2[4096u * 1024u];

// ============================ convert kernel ===============================
__global__ void conv_hi(const float* __restrict__ in, __half* __restrict__ hi, int n4)
{
    int i = blockIdx.x * blockDim.x + threadIdx.x;
    if (i >= n4) return;
    float4 v = ((const float4*)in)[i];
    ((__half2*)hi)[i * 2 + 0] = __halves2half2(__float2half_rn(v.x), __float2half_rn(v.y));
    ((__half2*)hi)[i * 2 + 1] = __halves2half2(__float2half_rn(v.z), __float2half_rn(v.w));
}

// ============================ ctx GEMM (fused combine) =====================
// CTA 128M x 192N, 8 warps (4M x 2N), warp tile 32x96.  (R7 config)
// Output byte: bits 0-2 ctx index, bits 3-5 per-score rescue flags.
__global__ __launch_bounds__(256, 1)
void gemm_ctx(const __half* __restrict__ Ahi, const __half* __restrict__ Bhi,
              int K, int O,
              unsigned char* __restrict__ ctxout, const float* __restrict__ T)
{
    extern __shared__ char smraw[];
    const uint32_t smb = smem_u32(smraw);
    const int tid  = threadIdx.x;
    const int lane = tid & 31;
    const int wid  = tid >> 5;
    const int wm   = wid & 3;
    const int wn   = wid >> 2;
    const int row0 = blockIdx.x * 128;
    const int col0 = blockIdx.y * 192;

    const __half* gA = Ahi + (size_t)row0 * K;
    const __half* gB = Bhi + (size_t)col0 * K;

    float acc[2][12][4];
#pragma unroll
    for (int i = 0; i < 2; i++)
#pragma unroll
        for (int j = 0; j < 12; j++)
#pragma unroll
            for (int q = 0; q < 4; q++) acc[i][j][q] = 0.0f;

    const int nk = K >> 5;

    auto issue = [&](int s) {
        uint32_t base = smb + (uint32_t)(s & (CSTAGES - 1)) * C_STAGE;
        int k0 = s * 32;
#pragma unroll
        for (int t = 0; t < 2; t++) {           // A: 512 cp16
            int id = tid + t * 256;
            int r  = id >> 2, c = id & 3;
            cp16(base + r * PITCH + c * 16, gA + (size_t)r * K + k0 + c * 8);
        }
#pragma unroll
        for (int t = 0; t < 3; t++) {           // B: 768 cp16
            int id = tid + t * 256;
            int r  = id >> 2, c = id & 3;
            cp16(base + C_AB + r * PITCH + c * 16, gB + (size_t)r * K + k0 + c * 8);
        }
        CP_COMMIT();
    };

#pragma unroll
    for (int s = 0; s < CSTAGES - 1; s++) issue(s);

    const uint32_t lrow = (uint32_t)(lane & 15);
    const uint32_t lhal = (uint32_t)(lane >> 4) * 16;

    for (int it = 0; it < nk; it++) {
        asm volatile("cp.async.wait_group 2;" ::: "memory");
        __syncthreads();
        int pf = it + CSTAGES - 1;
        if (pf < nk) issue(pf); else CP_COMMIT();

        uint32_t stg = smb + (uint32_t)(it & (CSTAGES - 1)) * C_STAGE;
#pragma unroll
        for (int k16 = 0; k16 < 2; k16++) {
            uint32_t koff = lhal + (uint32_t)k16 * 32;
            uint32_t ah[2][4];
#pragma unroll
            for (int mi = 0; mi < 2; mi++) {
                uint32_t ro = (uint32_t)(wm * 32 + mi * 16) + lrow;
                ldsm4(ah[mi], stg + ro * PITCH + koff);
            }
            uint32_t bh[12][2];
#pragma unroll
            for (int jj = 0; jj < 6; jj++) {
                uint32_t ro = (uint32_t)(wn * 96 + jj * 16) + lrow;
                uint32_t r4[4];
                ldsm4(r4, stg + C_AB + ro * PITCH + koff);
                bh[jj * 2][0] = r4[0]; bh[jj * 2][1] = r4[2];
                bh[jj * 2 + 1][0] = r4[1]; bh[jj * 2 + 1][1] = r4[3];
            }
#pragma unroll
            for (int mi = 0; mi < 2; mi++)
#pragma unroll
                for (int nj = 0; nj < 12; nj++) hmma(acc[mi][nj], ah[mi], bh[nj]);
        }
    }
    asm volatile("cp.async.wait_group 0;" ::: "memory");
    __syncthreads();

    // ---- stage scores into smem ----
    float* ssc = (float*)smraw;
    const int rr = lane >> 2;
    const int q2 = (lane & 3) * 2;
#pragma unroll
    for (int mi = 0; mi < 2; mi++) {
        int r_lo = wm * 32 + mi * 16 + rr;
        int r_hi = r_lo + 8;
#pragma unroll
        for (int nj = 0; nj < 12; nj++) {
            int c = wn * 96 + nj * 8 + q2;
            *(float2*)&ssc[r_lo * SC_PITCH + c] = make_float2(acc[mi][nj][0], acc[mi][nj][1]);
            *(float2*)&ssc[r_hi * SC_PITCH + c] = make_float2(acc[mi][nj][2], acc[mi][nj][3]);
        }
    }
    __syncthreads();

    // ---- combine: 128 rows x 64 o-groups -> 2048 uint32 words ----
    const int oc0 = col0 / 3;
#pragma unroll
    for (int w8 = 0; w8 < 8; w8++) {
        int word_id = tid + w8 * 256;
        int r  = word_id >> 4;
        int wo = word_id & 15;
        const float* sp = ssc + r * SC_PITCH + wo * 12;
        uint32_t word = 0;
#pragma unroll
        for (int j = 0; j < 4; j++) {
            int o = oc0 + wo * 4 + j;
            int c = 0;
#pragma unroll
            for (int s = 0; s < 3; s++) {
                float th = __ldg(T + o * 3 + s);
                float d  = sp[j * 3 + s] - th;
                c |= ((int)(d > 0.0f)) << s;
                c |= ((int)(fabsf(d) < RESCUE_TAU)) << (3 + s);
            }
            word |= (uint32_t)((unsigned char)c) << (j * 8);
        }
        *(uint32_t*)(ctxout + (size_t)(row0 + r) * O + oc0 + wo * 4) = word;
    }
}

// ============================ warp-cooperative fp64 rescue =================
__global__ void gln_rescue(unsigned char* __restrict__ ctx,
                           const float* __restrict__ z,
                           const float* __restrict__ H,
                           const float* __restrict__ T,
                           int total4, int O, int K)
{
    int i    = blockIdx.x * blockDim.x + threadIdx.x;
    int lane = threadIdx.x & 31;
    uint32_t w = (i < total4) ? ((const uint32_t*)ctx)[i] : 0u;
    unsigned m = __ballot_sync(0xFFFFFFFFu, (w & 0x38383838u) != 0u);
    while (m) {
        int src = __ffs(m) - 1; m &= m - 1;
        uint32_t sw = __shfl_sync(0xFFFFFFFFu, w, src);
        int si = __shfl_sync(0xFFFFFFFFu, i, src);
#pragma unroll
        for (int j = 0; j < 4; j++) {
            uint32_t byte = (sw >> (j * 8)) & 0xFF;
            if (!(byte & 0x38)) continue;
            int idx = si * 4 + j;
            int b = idx / O, o = idx - b * O;
            const float* zr = z + (size_t)b * K;
            int c = (int)(byte & 7);
#pragma unroll
            for (int s = 0; s < 3; s++) {
                if (!(byte & (8u << s))) continue;
                const float* hr = H + (size_t)(o * 3 + s) * K;
                double p0 = 0.0, p1 = 0.0;
                for (int k = lane; k < K; k += 64) {
                    p0 += (double)zr[k]      * (double)hr[k];
                    p1 += (double)zr[k + 32] * (double)hr[k + 32];
                }
                double part = p0 + p1;
#pragma unroll
                for (int off = 16; off; off >>= 1)
                    part += __shfl_down_sync(0xFFFFFFFFu, part, off);
                part = __shfl_sync(0xFFFFFFFFu, part, 0);
                c = (c & ~(1 << s)) | (((int)(part > (double)T[o * 3 + s])) << s);
            }
            if (lane == 0) ctx[idx] = (unsigned char)c;
        }
    }
}

// ============================ select GEMM ==================================
// CTA 128x128, 8 warps (4M x 2N), warp tile 32x64.  3-stage smem + 2 CTAs/SM.
// With 2 prefetched groups, wait_group 1 guarantees the consumed stage done.
// MODE 1: hidden -> fp16.  MODE 2: final -> fp32.
template <int MODE>
__global__ __launch_bounds__(256, 2)
void gemm_sel(const __half* __restrict__ Ahi, const __half* __restrict__ Bhi,
              int K, int O,
              const unsigned char* __restrict__ ctx, const float* __restrict__ bias,
              float* __restrict__ outf, __half* __restrict__ outh)
{
    extern __shared__ char smraw[];
    const uint32_t smb = smem_u32(smraw);
    const int tid  = threadIdx.x;
    const int lane = tid & 31;
    const int wid  = tid >> 5;
    const int wm   = wid & 3;
    const int wn   = wid >> 2;
    const int row0 = blockIdx.x * 128;
    const int col0 = blockIdx.y * 128;

    const __half* gA = Ahi + (size_t)row0 * K;
    const __half* gB = Bhi + (size_t)col0 * K;

    float acc[2][8][4];
#pragma unroll
    for (int i = 0; i < 2; i++)
#pragma unroll
        for (int j = 0; j < 8; j++)
#pragma unroll
            for (int q = 0; q < 4; q++) acc[i][j][q] = 0.0f;

    const int nk = K >> 5;

    auto issue = [&](int s) {
        uint32_t base = smb + (uint32_t)((unsigned)s % 3u) * S_STAGE;
        int k0 = s * 32;
#pragma unroll
        for (int t = 0; t < 4; t++) {           // 1024 cp16
            int id   = tid + t * 256;
            int tile = id >> 9;                 // 0..1
            int r    = (id >> 2) & 127;
            int c    = id & 3;
            const __half* g = tile ? gB : gA;
            cp16(base + tile * S_TILE + r * PITCH + c * 16,
                 g + (size_t)r * K + k0 + c * 8);
        }
        CP_COMMIT();
    };

#pragma unroll
    for (int s = 0; s < SSTAGES - 1; s++) issue(s);   // 2 groups in flight

    const uint32_t lrow = (uint32_t)(lane & 15);
    const uint32_t lhal = (uint32_t)(lane >> 4) * 16;

    for (int it = 0; it < nk; it++) {
        asm volatile("cp.async.wait_group 1;" ::: "memory");   // oldest done
        __syncthreads();
        int pf = it + SSTAGES - 1;
        if (pf < nk) issue(pf); else CP_COMMIT();

        uint32_t stg = smb + (uint32_t)((unsigned)it % 3u) * S_STAGE;
#pragma unroll
        for (int k16 = 0; k16 < 2; k16++) {
            uint32_t koff = lhal + (uint32_t)k16 * 32;
            uint32_t ah[2][4];
#pragma unroll
            for (int mi = 0; mi < 2; mi++) {
                uint32_t ro = (uint32_t)(wm * 32 + mi * 16) + lrow;
                ldsm4(ah[mi], stg + ro * PITCH + koff);
            }
            uint32_t bh[8][2];
#pragma unroll
            for (int jj = 0; jj < 4; jj++) {
                uint32_t ro = (uint32_t)(wn * 64 + jj * 16) + lrow;
                uint32_t r4[4];
                ldsm4(r4, stg + S_TILE + ro * PITCH + koff);
                bh[jj * 2][0] = r4[0]; bh[jj * 2][1] = r4[2];
                bh[jj * 2 + 1][0] = r4[1]; bh[jj * 2 + 1][1] = r4[3];
            }
#pragma unroll
            for (int mi = 0; mi < 2; mi++)
#pragma unroll
                for (int nj = 0; nj < 8; nj++) hmma(acc[mi][nj], ah[mi], bh[nj]);
        }
    }

    // ---- 1-of-8 select epilogue ----
    const int rr = lane >> 2;
    const int q2 = (lane & 3) * 2;
#pragma unroll
    for (int mi = 0; mi < 2; mi++) {
        int r_lo = row0 + wm * 32 + mi * 16 + rr;
        int r_hi = r_lo + 8;
#pragma unroll
        for (int nj = 0; nj < 8; nj++) {
            int o   = (col0 + wn * 64 + nj * 8) >> 3;
            int cb0 = ctx[(size_t)r_lo * O + o] & 7;
            int cb1 = ctx[(size_t)r_hi * O + o] & 7;
            if (cb0 == q2 || cb0 == q2 + 1) {
                float v = (cb0 == q2) ? acc[mi][nj][0] : acc[mi][nj][1];
                if (bias) v += bias[o * 8 + cb0];
                size_t idx = (size_t)r_lo * O + o;
                if (MODE == 1) outh[idx] = __float2half_rn(v);
                else           outf[idx] = v;
            }
            if (cb1 == q2 || cb1 == q2 + 1) {
                float v = (cb1 == q2) ? acc[mi][nj][2] : acc[mi][nj][3];
                if (bias) v += bias[o * 8 + cb1];
                size_t idx = (size_t)r_hi * O + o;
                if (MODE == 1) outh[idx] = __float2half_rn(v);
                else           outf[idx] = v;
            }
        }
    }
}

// ============================ host =========================================
extern "C" void kernel_launch(void* const* d_in, const int* in_sizes, int n_in,
                              void* d_out, int out_size)
{
    const float* x  = (const float*)d_in[0];
    const float* W0 = (const float*)d_in[1];
    const float* W1 = (const float*)d_in[2];
    const float* W2 = (const float*)d_in[3];
    const float* b1 = (const float*)d_in[4];
    const float* b2 = (const float*)d_in[5];
    const float* H0 = (const float*)d_in[6];
    const float* T0 = (const float*)d_in[7];
    const float* H1 = (const float*)d_in[8];
    const float* T1 = (const float*)d_in[9];
    const float* H2 = (const float*)d_in[10];
    const float* T2 = (const float*)d_in[11];
    float* out = (float*)d_out;

    void *pxh, *pa, *pb, *pwa, *pwb, *pc0, *pc1, *pc2;
    cudaGetSymbolAddress(&pxh, g_xh);
    cudaGetSymbolAddress(&pa,  g_hA);  cudaGetSymbolAddress(&pb,  g_hB);
    cudaGetSymbolAddress(&pwa, g_whA); cudaGetSymbolAddress(&pwb, g_whB);
    cudaGetSymbolAddress(&pc0, g_ctx0); cudaGetSymbolAddress(&pc1, g_ctx1);
    cudaGetSymbolAddress(&pc2, g_ctx2);
    __half* xh  = (__half*)pxh;
    __half* hA  = (__half*)pa;   __half* hB  = (__half*)pb;
    __half* whA = (__half*)pwa;  __half* whB = (__half*)pwb;
    unsigned char* c0 = (unsigned char*)pc0;
    unsigned char* c1 = (unsigned char*)pc1;
    unsigned char* c2 = (unsigned char*)pc2;

    const int B = 4096, DIN = 1024, DLAT = 2048, DOUT = 1024;

    cudaFuncSetAttribute(gemm_ctx,    cudaFuncAttributeMaxDynamicSharedMemorySize, C_SMEM);
    cudaFuncSetAttribute(gemm_sel<1>, cudaFuncAttributeMaxDynamicSharedMemorySize, S_SMEM);
    cudaFuncSetAttribute(gemm_sel<2>, cudaFuncAttributeMaxDynamicSharedMemorySize, S_SMEM);

    auto conv = [](const float* in, __half* dst, size_t n) {
        int n4 = (int)(n / 4);
        conv_hi<<<(n4 + 255) / 256, 256>>>(in, dst, n4);
    };

    // Launch order keeps the profiled launch (0-based #3) on gemm_ctx.
    conv(x,  xh,  (size_t)B * DIN);                                  // 0
    conv(H0, whA, (size_t)DLAT * 3 * DIN);                           // 1
    conv(W0, whB, (size_t)DLAT * 8 * DIN);                           // 2
    gemm_ctx<<<dim3(B / 128, (DLAT * 3) / 192), 256, C_SMEM>>>(      // 3
        xh, whA, DIN, DLAT, c0, T0);
    gln_rescue<<<(B * DLAT / 4 + 255) / 256, 256>>>(                 // 4
        c0, x, H0, T0, B * DLAT / 4, DLAT, DIN);
    gemm_sel<1><<<dim3(B / 128, (DLAT * 8) / 128), 256, S_SMEM>>>(   // 5
        xh, whB, DIN, DLAT, c0, nullptr, nullptr, hA);

    conv(H1, whA, (size_t)DLAT * 3 * DIN);                           // 6
    gemm_ctx<<<dim3(B / 128, (DLAT * 3) / 192), 256, C_SMEM>>>(      // 7
        xh, whA, DIN, DLAT, c1, T1);
    gln_rescue<<<(B * DLAT / 4 + 255) / 256, 256>>>(                 // 8
        c1, x, H1, T1, B * DLAT / 4, DLAT, DIN);
    conv(W1, whB, (size_t)DLAT * 8 * DLAT);                          // 9
    gemm_sel<1><<<dim3(B / 128, (DLAT * 8) / 128), 256, S_SMEM>>>(   // 10
        hA, whB, DLAT, DLAT, c1, b1, nullptr, hB);

    conv(H2, whA, (size_t)DOUT * 3 * DIN);                           // 11
    gemm_ctx<<<dim3(B / 128, (DOUT * 3) / 192), 256, C_SMEM>>>(      // 12
        xh, whA, DIN, DOUT, c2, T2);
    gln_rescue<<<(B * DOUT / 4 + 255) / 256, 256>>>(                 // 13
        c2, x, H2, T2, B * DOUT / 4, DOUT, DIN);
    conv(W2, whB, (size_t)DOUT * 8 * DLAT);                          // 14
    gemm_sel<2><<<dim3(B / 128, (DOUT * 8) / 128), 256, S_SMEM>>>(   // 15
        hB, whB, DLAT, DOUT, c2, b2, out, nullptr);

    (void)in_sizes; (void)n_in; (void)out_size;
}